// round 17
// baseline (speedup 1.0000x reference)
#include <cuda_runtime.h>
#include <cuda_fp16.h>
#include <cstdint>
#include <math.h>

// ---------------- problem constants ----------------
// B=32, C=320 (5 co-tiles of 64), H=W=64, CTX_DIM=1024, CTX_HW=16
// GEMM1: 1040 in-ch = 65 chunks of 16; GEMM2: 320 = 20 chunks
// fp16 mma m16n8k16, tap-major K: 9 k-steps per 16-ch chunk (k = 16 channels)
#define NCH1 65
#define NCH2 20
#define CHWH 9216      // halves per weight chunk tile: 4 mi * 9 t * 32 lane * 8

// smem (bytes): per buffer A tile 18432 + halo 18 rows * 24 cells * 32B = 13824
#define SMA   18432
#define SMHB  13824
#define SMBUF 32256
#define SMREQ 64512

// ---------------- device scratch ----------------
__device__ __half g_ctxh[32 * 65 * 256 * 16];   // interleaved fp16 ctx
__device__ __half g_w1h [5 * NCH1 * CHWH];      // fragment fp16 w_in
__device__ __half g_w2h [5 * NCH2 * CHWH];      // fragment fp16 w_out
__device__ __half g_midh[32 * 20 * 256 * 16];   // interleaved fp16 silu(conv1)
__device__ float  g_cx  [32 * 320 * 256];       // conv2 out (NCHW fp32)

__device__ __forceinline__ uint32_t smem_u32(const void* p) {
    uint32_t a;
    asm("{ .reg .u64 t; cvta.to.shared.u64 t, %1; cvt.u32.u64 %0, t; }" : "=r"(a) : "l"(p));
    return a;
}
__device__ __forceinline__ void cp16(uint32_t d, const void* s) {
    asm volatile("cp.async.cg.shared.global [%0], [%1], 16;" :: "r"(d), "l"(s));
}
#define CP_COMMIT() asm volatile("cp.async.commit_group;" ::: "memory")
#define CP_WAIT0()  asm volatile("cp.async.wait_group 0;" ::: "memory")

__device__ __forceinline__ void mma16(float* d, const uint4 a, const uint2 b) {
    asm volatile(
        "mma.sync.aligned.m16n8k16.row.col.f32.f16.f16.f32 "
        "{%0,%1,%2,%3}, {%4,%5,%6,%7}, {%8,%9}, {%0,%1,%2,%3};\n"
        : "+f"(d[0]), "+f"(d[1]), "+f"(d[2]), "+f"(d[3])
        : "r"(a.x), "r"(a.y), "r"(a.z), "r"(a.w), "r"(b.x), "r"(b.y));
}

// interleave position of channel ch (0..15): groups j hold {2j,2j+1,2j+8,2j+9}
__host__ __device__ __forceinline__ int ipos(int ch) {
    return ((ch & 7) >> 1) * 4 + (ch & 1) + ((ch >> 3) & 1) * 2;
}

// ---------------- K0: weight prep -> fp16 fragment tiles (tap-major, M=64) ----------------
// layout: [cot 5][chunk][mi 4][t 9][lane 32][8 halves]
__global__ void prep_w(const float* __restrict__ w_in, const float* __restrict__ w_out,
                       __half* __restrict__ w1h, __half* __restrict__ w2h) {
    const int N1 = 5 * NCH1 * CHWH;
    const int N2 = 5 * NCH2 * CHWH;
    int i = blockIdx.x * blockDim.x + threadIdx.x;
    if (i >= N1 + N2) return;
    bool first = (i < N1);
    int j = first ? i : i - N1;
    int NCH = first ? NCH1 : NCH2;
    int h    = j & 7;
    int lane = (j >> 3) & 31;
    int t    = (j >> 8) % 9;
    int rest = (j >> 8) / 9;
    int mi   = rest & 3;
    int r2   = rest >> 2;
    int chunk = r2 % NCH, cot = r2 / NCH;
    int g = lane >> 2, r = lane & 3;
    int row = cot * 64 + mi * 16 + g + ((h >> 1) & 1) * 8;
    int ch  = 2 * r + (h & 1) + ((h >> 2) & 1) * 8;
    int ci  = chunk * 16 + ch;
    float v = 0.f;
    if (first) {
        if (ci < 1026) v = w_in[(row * 1026 + ci) * 9 + t];
        w1h[j] = __float2half_rn(v);
    } else {
        v = w_out[(row * 320 + ci) * 9 + t];
        w2h[j] = __float2half_rn(v);
    }
}

// ---------------- K1: ctx -> fp16 interleaved pixel-major ----------------
__global__ void build_ctx(const float* __restrict__ ctx, const float* __restrict__ ind,
                          __half* __restrict__ out) {
    __shared__ __half s[256 * 16];
    int cb = blockIdx.x, b = blockIdx.y, tid = threadIdx.x;
    int ci0 = cb * 16;
    #pragma unroll
    for (int j = 0; j < 16; j++) {
        int idx = tid + j * 256;
        int p = idx >> 4, ch = idx & 15;
        int ci = ci0 + ch;
        float v;
        if (ci < 1024)      v = ctx[((size_t)b * 256 + p) * 1024 + ci];
        else if (ci < 1026) v = ind[b * 2 + (ci - 1024)];
        else                v = 0.f;
        s[p * 16 + ipos(ch)] = __float2half_rn(v);
    }
    __syncthreads();
    const uint4* su = (const uint4*)s;
    uint4* du = (uint4*)out + ((size_t)(b * 65 + cb) * 256 + tid) * 2;
    du[0] = su[tid * 2];
    du[1] = su[tid * 2 + 1];
}

// ---------------- staging one chunk (A tile + full-image halo interior) ----------------
__device__ __forceinline__ void stage_chunk(uint32_t sb, int buf,
                                            const __half* __restrict__ wchunk,
                                            const __half* __restrict__ xb,
                                            int c, int tid) {
    uint32_t base = sb + buf * SMBUF;
    const char* ws = (const char*)wchunk;
    #pragma unroll
    for (int i = 0; i < 4; i++) {
        int idx = tid + i * 256;
        cp16(base + idx * 16, ws + idx * 16);           // 1024 of 1152
    }
    if (tid < 128) {
        int idx = tid + 1024;
        cp16(base + idx * 16, ws + idx * 16);           // remaining 128
    }
    uint32_t hd = base + SMA;
    #pragma unroll
    for (int i = 0; i < 2; i++) {
        int idx = tid + i * 256;                        // 0..511
        int hsel = idx & 1;
        int px   = (idx >> 1) & 15;
        int py   = idx >> 5;                            // 0..15
        const char* src = (const char*)(xb + ((size_t)c * 256 + py * 16 + px) * 16)
                          + hsel * 16;
        cp16(hd + (((py + 1) * 24 + px + 4) * 32) + hsel * 16, src);
    }
    CP_COMMIT();
}

// ---------------- conv as implicit-im2col GEMM (mma.sync fp16 k16) ----------------
// CTA = 64 co x 256 px, 256 thr = 8 warps (1m x 8n), warptile 64x32, occ 2
// grid (5 cot, 32 batch) = 160 CTAs -> single wave at occ 2
template <bool SILU>
__global__ __launch_bounds__(256, 2)
void conv_gemm(const __half* __restrict__ gW, int nch,
               const __half* __restrict__ gX,
               const float* __restrict__ bias,
               void* __restrict__ gOut) {
    extern __shared__ char dsm[];
    uint32_t sb = smem_u32(dsm);

    int tid  = threadIdx.x;
    int lane = tid & 31;
    int nw   = tid >> 5;             // warp = n-tile 0..7 (32 px each)
    int g    = lane >> 2;
    int r    = lane & 3;

    int cot   = blockIdx.x;          // 0..4
    int batch = blockIdx.y;

    const __half* xb  = gX + (size_t)batch * nch * 256 * 16;
    const __half* wct = gW + (size_t)cot * nch * CHWH;

    // zero both halo buffers once (borders stay zero forever)
    #pragma unroll
    for (int i = tid; i < 864; i += 256) {
        *(uint4*)(dsm + 0 * SMBUF + SMA + i * 16) = make_uint4(0, 0, 0, 0);
        *(uint4*)(dsm + 1 * SMBUF + SMA + i * 16) = make_uint4(0, 0, 0, 0);
    }
    __syncthreads();

    // per-thread B base offsets (bytes within halo); 32B cells, conflict-free
    int pb[4];
    #pragma unroll
    for (int nj = 0; nj < 4; nj++) {
        int pl = nw * 32 + nj * 8 + g;   // 0..255
        int py = pl >> 4, px = pl & 15;
        pb[nj] = ((py + 1) * 24 + px + 4) * 32 + r * 8;
    }

    float acc[4][4][4];
    #pragma unroll
    for (int mi = 0; mi < 4; mi++)
        #pragma unroll
        for (int nj = 0; nj < 4; nj++)
            #pragma unroll
            for (int j = 0; j < 4; j++) acc[mi][nj][j] = 0.f;

    stage_chunk(sb, 0, wct, xb, 0, tid);

    for (int c = 0; c < nch; ++c) {
        int buf = c & 1;
        CP_WAIT0();
        __syncthreads();
        if (c + 1 < nch)
            stage_chunk(sb, buf ^ 1, wct + (size_t)(c + 1) * CHWH, xb, c + 1, tid);

        const uint4* sA = (const uint4*)(dsm + buf * SMBUF);
        const char*  sH = dsm + buf * SMBUF + SMA;

        #pragma unroll
        for (int t = 0; t < 9; t++) {
            int toff = (t / 3 - 1) * 768 + (t % 3 - 1) * 32;
            uint4 a0 = sA[(0 * 9 + t) * 32 + lane];
            uint4 a1 = sA[(1 * 9 + t) * 32 + lane];
            uint4 a2 = sA[(2 * 9 + t) * 32 + lane];
            uint4 a3 = sA[(3 * 9 + t) * 32 + lane];
            #pragma unroll
            for (int nj = 0; nj < 4; nj++) {
                uint2 b = *(const uint2*)(sH + pb[nj] + toff);
                mma16(acc[0][nj], a0, b);
                mma16(acc[1][nj], a1, b);
                mma16(acc[2][nj], a2, b);
                mma16(acc[3][nj], a3, b);
            }
        }
        __syncthreads();
    }

    // ---------------- epilogue ----------------
    if (SILU) {
        __half* ob = (__half*)gOut;
        #pragma unroll
        for (int mi = 0; mi < 4; mi++) {
            int cb = batch * 20 + cot * 4 + mi;
            #pragma unroll
            for (int half = 0; half < 2; half++) {
                int m   = cot * 64 + mi * 16 + g + half * 8;
                int pos = (g >> 1) * 4 + (g & 1) + half * 2;
                float bz = __ldg(bias + m);
                #pragma unroll
                for (int nj = 0; nj < 4; nj++) {
                    int p = nw * 32 + nj * 8 + 2 * r;
                    #pragma unroll
                    for (int col = 0; col < 2; col++) {
                        float v = acc[mi][nj][half * 2 + col] + bz;
                        v = v / (1.f + expf(-v));
                        ob[((size_t)cb * 256 + p + col) * 16 + pos] = __float2half_rn(v);
                    }
                }
            }
        }
    } else {
        float* ob = (float*)gOut + (size_t)batch * 320 * 256;
        #pragma unroll
        for (int mi = 0; mi < 4; mi++) {
            #pragma unroll
            for (int half = 0; half < 2; half++) {
                int m = cot * 64 + mi * 16 + g + half * 8;
                float bz = __ldg(bias + m);
                #pragma unroll
                for (int nj = 0; nj < 4; nj++) {
                    int p = nw * 32 + nj * 8 + 2 * r;
                    float v0 = acc[mi][nj][half * 2 + 0] + bz;
                    float v1 = acc[mi][nj][half * 2 + 1] + bz;
                    *(float2*)(ob + (size_t)m * 256 + p) = make_float2(v0, v1);
                }
            }
        }
    }
}

// ---------------- K4: bbox scatter-add ----------------
__global__ void scatter_add(const float* __restrict__ gx, const float* __restrict__ cx,
                            const float* __restrict__ bbox, float* __restrict__ out) {
    int i = blockIdx.x * blockDim.x + threadIdx.x;
    int b = i / 327680;
    int rem = i - b * 327680;
    int ch = rem >> 10;
    int rem2 = rem & 1023;
    int y = rem2 >> 4;
    int x0 = (rem2 & 15) << 2;

    float4 gv = *(const float4*)(gx + (size_t)i * 4);
    float o[4] = {gv.x, gv.y, gv.z, gv.w};

    int x1  = (int)(bbox[b * 4 + 0] * 64.f);
    int y1  = (int)(bbox[b * 4 + 1] * 64.f);
    int x2i = (int)(bbox[b * 4 + 2] * 64.f);
    int y2i = (int)(bbox[b * 4 + 3] * 64.f);
    int x2 = x2i > x1 + 1 ? x2i : x1 + 1;
    int y2 = y2i > y1 + 1 ? y2i : y1 + 1;
    bool ok = (y2 <= 64) && (x2 <= 64) && (y1 >= 0) && (x1 >= 0);

    if (ok && y >= y1 && y < y2) {
        int sy = ((y - y1) * 16) / (y2 - y1);
        sy = sy < 0 ? 0 : (sy > 15 ? 15 : sy);
        const float* row = cx + ((size_t)b * 320 + ch) * 256 + sy * 16;
        #pragma unroll
        for (int e = 0; e < 4; e++) {
            int x = x0 + e;
            if (x >= x1 && x < x2) {
                int sx = ((x - x1) * 16) / (x2 - x1);
                sx = sx < 0 ? 0 : (sx > 15 ? 15 : sx);
                o[e] += row[sx];
            }
        }
    }
    *(float4*)(out + (size_t)i * 4) = make_float4(o[0], o[1], o[2], o[3]);
}

// ---------------- launcher ----------------
extern "C" void kernel_launch(void* const* d_in, const int* in_sizes, int n_in,
                              void* d_out, int out_size) {
    (void)in_sizes; (void)n_in; (void)out_size;
    const float* global_x  = (const float*)d_in[0];
    const float* context   = (const float*)d_in[1];
    const float* indicator = (const float*)d_in[2];
    const float* bbox      = (const float*)d_in[3];
    const float* w_in      = (const float*)d_in[4];
    const float* b_in      = (const float*)d_in[5];
    const float* w_out     = (const float*)d_in[6];
    const float* b_out     = (const float*)d_in[7];
    float* out = (float*)d_out;

    __half *pctx, *pw1, *pw2, *pmid;
    float *pcx;
    cudaGetSymbolAddress((void**)&pctx, g_ctxh);
    cudaGetSymbolAddress((void**)&pw1,  g_w1h);
    cudaGetSymbolAddress((void**)&pw2,  g_w2h);
    cudaGetSymbolAddress((void**)&pmid, g_midh);
    cudaGetSymbolAddress((void**)&pcx,  g_cx);

    cudaFuncSetAttribute(conv_gemm<true >, cudaFuncAttributeMaxDynamicSharedMemorySize, SMREQ);
    cudaFuncSetAttribute(conv_gemm<false>, cudaFuncAttributeMaxDynamicSharedMemorySize, SMREQ);

    const int nprep = 5 * NCH1 * CHWH + 5 * NCH2 * CHWH;
    prep_w<<<(nprep + 255) / 256, 256>>>(w_in, w_out, pw1, pw2);
    build_ctx<<<dim3(65, 32), 256>>>(context, indicator, pctx);
    conv_gemm<true ><<<dim3(5, 32), 256, SMREQ>>>(pw1, NCH1, pctx, b_in,  (void*)pmid);
    conv_gemm<false><<<dim3(5, 32), 256, SMREQ>>>(pw2, NCH2, pmid, b_out, (void*)pcx);
    scatter_add<<<40960, 256>>>(global_x, pcx, bbox, out);
}